// round 16
// baseline (speedup 1.0000x reference)
#include <cuda_runtime.h>
#include <cuda_fp16.h>
#include <cstdint>

#define FULL 0xffffffffu

static const int MAXN = 100000;
static const int MAXE = 2000000;

// ---------------- scratch (device globals) ----------------
__device__ float  g_feat0[MAXN * 64];
__device__ float  g_feat1[MAXN * 64];
__device__ float  g_hbuf[MAXN * 64];
__device__ __half g_aggx[(size_t)MAXN * 512];   // per-head alpha-weighted x sums
__device__ uint32_t g_wstk[256 * 40];           // packed half2 Wstack (k-pairs)
__device__ float  g_als[MAXN * 8];
__device__ float  g_ald[MAXN * 8];
__device__ float  g_wproj[128 * 16];
__device__ int    g_cnt[MAXN];
__device__ int    g_cur[MAXN];
__device__ int    g_off[MAXN + 1];
__device__ int    g_csr[MAXE];
__device__ int    g_bsum[128];
__device__ int    g_bsum2[130];

// ---------------- CSR build ----------------
__global__ void k_zero_cnt(int n) {
    int i = blockIdx.x * blockDim.x + threadIdx.x;
    if (i < n) g_cnt[i] = 0;
}

__global__ void k_count(const int* __restrict__ dst, int E) {
    int e = blockIdx.x * blockDim.x + threadIdx.x;
    if (e < E) atomicAdd(&g_cnt[dst[e]], 1);
}

__global__ void k_scan1(int n) {
    __shared__ int sh[1024];
    int t = threadIdx.x;
    int i = blockIdx.x * 1024 + t;
    int v = (i < n) ? g_cnt[i] : 0;
    sh[t] = v;
    __syncthreads();
    for (int o = 1; o < 1024; o <<= 1) {
        int x = (t >= o) ? sh[t - o] : 0;
        __syncthreads();
        sh[t] += x;
        __syncthreads();
    }
    if (i < n) g_off[i] = sh[t] - v;
    if (t == 1023) g_bsum[blockIdx.x] = sh[1023];
}

__global__ void k_scan2(int nblk) {
    __shared__ int sh[128];
    int t = threadIdx.x;
    int v = (t < nblk) ? g_bsum[t] : 0;
    sh[t] = v;
    __syncthreads();
    for (int o = 1; o < 128; o <<= 1) {
        int x = (t >= o) ? sh[t - o] : 0;
        __syncthreads();
        sh[t] += x;
        __syncthreads();
    }
    g_bsum2[t] = sh[t] - v;
    if (t == nblk - 1) g_bsum2[nblk] = sh[t];
}

__global__ void k_scan3(int n, int nblk) {
    int i = blockIdx.x * blockDim.x + threadIdx.x;
    if (i < n) {
        int v = g_off[i] + g_bsum2[i >> 10];
        g_off[i] = v;
        g_cur[i] = v;
    } else if (i == n) {
        g_off[n] = g_bsum2[nblk];
    }
}

__global__ void k_fill(const int* __restrict__ src, const int* __restrict__ dst, int E) {
    int e = blockIdx.x * blockDim.x + threadIdx.x;
    if (e < E) {
        int d = dst[e];
        int pos = atomicAdd(&g_cur[d], 1);
        g_csr[pos] = src[e];
    }
}

// ---------------- mma / cp.async helpers --------------------------------------
__device__ __forceinline__ void mma_tf32(float* c, uint32_t a0, uint32_t a1,
                                         uint32_t a2, uint32_t a3,
                                         uint32_t b0, uint32_t b1) {
    asm volatile(
        "mma.sync.aligned.m16n8k8.row.col.f32.tf32.tf32.f32 "
        "{%0,%1,%2,%3}, {%4,%5,%6,%7}, {%8,%9}, {%0,%1,%2,%3};"
        : "+f"(c[0]), "+f"(c[1]), "+f"(c[2]), "+f"(c[3])
        : "r"(a0), "r"(a1), "r"(a2), "r"(a3), "r"(b0), "r"(b1));
}

__device__ __forceinline__ void mma_f16(float* c, uint32_t a0, uint32_t a1,
                                        uint32_t a2, uint32_t a3,
                                        uint32_t b0, uint32_t b1) {
    asm volatile(
        "mma.sync.aligned.m16n8k16.row.col.f32.f16.f16.f32 "
        "{%0,%1,%2,%3}, {%4,%5,%6,%7}, {%8,%9}, {%0,%1,%2,%3};"
        : "+f"(c[0]), "+f"(c[1]), "+f"(c[2]), "+f"(c[3])
        : "r"(a0), "r"(a1), "r"(a2), "r"(a3), "r"(b0), "r"(b1));
}

__device__ __forceinline__ void cp16(void* dst_smem, const void* src, int src_sz) {
    uint32_t d = (uint32_t)__cvta_generic_to_shared(dst_smem);
    asm volatile("cp.async.ca.shared.global [%0], [%1], 16, %2;"
                 :: "r"(d), "l"(src), "r"(src_sz));
}
__device__ __forceinline__ void cp_commit() {
    asm volatile("cp.async.commit_group;");
}
template <int N>
__device__ __forceinline__ void cp_wait() {
    asm volatile("cp.async.wait_group %0;" :: "n"(N));
}

__device__ __forceinline__ void store_pair(float* p, float v0, float v1) {
    *(float2*)p = make_float2(v0, v1);
}

// ---------------- TF32 GEMM (layers 1-4), 3-stage cp.async pipeline -----------
// One __syncthreads per k-iter: stage(t+2) writes buf (t+2)%3 which is disjoint
// from compute's buf t%3, and its previous readers (iter t-1) retired before
// the top-of-iter barrier.
__global__ __launch_bounds__(256) void k_gemm(const float* __restrict__ A,
                                              const float* __restrict__ B,
                                              float* __restrict__ C,
                                              const float* __restrict__ a_s,
                                              const float* __restrict__ a_d,
                                              int nrows, int K, int M) {
    __shared__ float As[3][128][20];
    __shared__ float Bs[3][16][72];
    int tid  = threadIdx.x;
    int lane = tid & 31, wid = tid >> 5;
    int wm = wid & 3, wn = wid >> 2;
    int tig = lane & 3, grp = lane >> 2;
    int row0 = blockIdx.x * 128, col0 = blockIdx.y * 64;

    float acc[2][4][4] = {};

    int a_r = tid >> 1, a_part2 = (tid & 1) * 2;
    int b_r = tid >> 4, b_part = tid & 15;

    auto stage = [&](int kc, int buf) {
#pragma unroll
        for (int q = 0; q < 2; ++q) {
            int part = a_part2 + q;
            int gr = row0 + a_r;
            int grc = gr < nrows ? gr : nrows - 1;
            cp16(&As[buf][a_r][part * 4],
                 A + (size_t)grc * K + kc + part * 4,
                 gr < nrows ? 16 : 0);
        }
        cp16(&Bs[buf][b_r][b_part * 4],
             B + (size_t)(kc + b_r) * M + col0 + b_part * 4, 16);
    };

    int T = K >> 4;
    stage(0, 0);
    cp_commit();
    if (T > 1) {
        stage(16, 1);
        cp_commit();
    }

    for (int t = 0; t < T; ++t) {
        if (t + 1 < T) cp_wait<1>();
        else           cp_wait<0>();
        __syncthreads();
        int buf = t % 3;
#pragma unroll
        for (int ks = 0; ks < 2; ++ks) {
            uint32_t bf[4][2];
#pragma unroll
            for (int nj = 0; nj < 4; ++nj) {
                int c = wn * 32 + nj * 8 + grp;
                bf[nj][0] = __float_as_uint(Bs[buf][ks * 8 + tig][c]);
                bf[nj][1] = __float_as_uint(Bs[buf][ks * 8 + tig + 4][c]);
            }
#pragma unroll
            for (int mi = 0; mi < 2; ++mi) {
                int r = wm * 32 + mi * 16 + grp;
                uint32_t a0 = __float_as_uint(As[buf][r][ks * 8 + tig]);
                uint32_t a1 = __float_as_uint(As[buf][r + 8][ks * 8 + tig]);
                uint32_t a2 = __float_as_uint(As[buf][r][ks * 8 + tig + 4]);
                uint32_t a3 = __float_as_uint(As[buf][r + 8][ks * 8 + tig + 4]);
#pragma unroll
                for (int nj = 0; nj < 4; ++nj)
                    mma_tf32(acc[mi][nj], a0, a1, a2, a3, bf[nj][0], bf[nj][1]);
            }
        }
        if (t + 2 < T) {
            stage((t + 2) << 4, (t + 2) % 3);
            cp_commit();
        }
    }

#pragma unroll
    for (int mi = 0; mi < 2; ++mi) {
        int r0 = row0 + wm * 32 + mi * 16 + grp;
#pragma unroll
        for (int nj = 0; nj < 4; ++nj) {
            int col = col0 + wn * 32 + nj * 8 + 2 * tig;
            if (r0 < nrows)
                store_pair(C + (size_t)r0 * M + col, acc[mi][nj][0], acc[mi][nj][1]);
            if (r0 + 8 < nrows)
                store_pair(C + (size_t)(r0 + 8) * M + col, acc[mi][nj][2], acc[mi][nj][3]);
            {   // fused attention logits (M==64)
                int head = wn * 4 + nj;
                float as0 = __ldg(&a_s[head * 8 + 2 * tig]);
                float as1 = __ldg(&a_s[head * 8 + 2 * tig + 1]);
                float ad0 = __ldg(&a_d[head * 8 + 2 * tig]);
                float ad1 = __ldg(&a_d[head * 8 + 2 * tig + 1]);
                float ds0 = acc[mi][nj][0] * as0 + acc[mi][nj][1] * as1;
                float dd0 = acc[mi][nj][0] * ad0 + acc[mi][nj][1] * ad1;
                float ds1 = acc[mi][nj][2] * as0 + acc[mi][nj][3] * as1;
                float dd1 = acc[mi][nj][2] * ad0 + acc[mi][nj][3] * ad1;
#pragma unroll
                for (int d = 1; d <= 2; d <<= 1) {
                    ds0 += __shfl_xor_sync(FULL, ds0, d);
                    dd0 += __shfl_xor_sync(FULL, dd0, d);
                    ds1 += __shfl_xor_sync(FULL, ds1, d);
                    dd1 += __shfl_xor_sync(FULL, dd1, d);
                }
                if (tig == 0) {
                    if (r0 < nrows) {
                        g_als[r0 * 8 + head] = ds0;
                        g_ald[r0 * 8 + head] = dd0;
                    }
                    if (r0 + 8 < nrows) {
                        g_als[(r0 + 8) * 8 + head] = ds1;
                        g_ald[(r0 + 8) * 8 + head] = dd1;
                    }
                }
            }
        }
    }
}

// ---------------- layer-5 prep: wproj + wstk fused -----------------------------
// idx < K*16: wproj.  idx >= K*16: wstk (packed half2 Wstack with mean folded).
__global__ void k_w5prep(const float* __restrict__ W5, const float* __restrict__ a_s,
                         const float* __restrict__ a_d) {
    int idx = blockIdx.x * blockDim.x + threadIdx.x;
    const int KP = 64 * 16;
    if (idx < KP) {
        int k = idx >> 4, l = idx & 15;
        int h = l & 7;
        const float* a = (l >= 8) ? a_d : a_s;
        float s = 0.f;
        for (int c = 0; c < 40; ++c)
            s = fmaf(W5[(size_t)k * 320 + h * 40 + c], __ldg(&a[h * 40 + c]), s);
        g_wproj[idx] = s;
        return;
    }
    int j = idx - KP;
    if (j >= 256 * 40) return;
    int k2 = j / 40, c = j % 40;
    int kk = 2 * k2;
    int h = kk >> 6, k0 = kk & 63;
    float lo = W5[(size_t)k0 * 320 + h * 40 + c] * 0.125f;
    float hi = W5[(size_t)(k0 + 1) * 320 + h * 40 + c] * 0.125f;
    __half2 v = __floats2half2_rn(lo, hi);
    g_wstk[k2 * 40 + c] = *(uint32_t*)&v;
}

__global__ void k_alfeat(const float* __restrict__ feat, int n) {
    int node = blockIdx.x * blockDim.x + threadIdx.x;
    if (node >= n) return;
    const float4* fp = (const float4*)(feat + (size_t)node * 64);
    float acc[16];
#pragma unroll
    for (int l = 0; l < 16; ++l) acc[l] = 0.f;
#pragma unroll 4
    for (int k4 = 0; k4 < 16; ++k4) {
        float4 v = fp[k4];
        const float* wp = &g_wproj[k4 * 4 * 16];
#pragma unroll
        for (int l = 0; l < 16; ++l)
            acc[l] += v.x * __ldg(&wp[l])      + v.y * __ldg(&wp[16 + l])
                    + v.z * __ldg(&wp[32 + l]) + v.w * __ldg(&wp[48 + l]);
    }
#pragma unroll
    for (int l = 0; l < 8; ++l) g_als[node * 8 + l] = acc[l];
#pragma unroll
    for (int l = 8; l < 16; ++l) g_ald[node * 8 + l - 8] = acc[l];
}

// ---------------- single-pass aggregation, layers 1-4 (H=8, C=8) -------------
__global__ __launch_bounds__(256) void k_agg64(const float* __restrict__ hfeat,
                                               const float* __restrict__ bias,
                                               float* __restrict__ outf, int n) {
    int gw = (blockIdx.x * blockDim.x + threadIdx.x) >> 5;
    if (gw >= n) return;
    int lane = threadIdx.x & 31;
    int hq = lane >> 2;
    int beg = g_off[gw], end = g_off[gw + 1];

    float ald_q = g_ald[gw * 8 + hq];
    float eself = g_als[gw * 8 + hq] + ald_q;
    eself = eself > 0.f ? eself : 0.2f * eself;

    float s = 1.f;
    float2 acc = *(const float2*)(hfeat + (size_t)gw * 64 + 2 * lane);

#pragma unroll 4
    for (int i = beg; i < end; ++i) {
        int src = g_csr[i];
        float e = __ldg(&g_als[src * 8 + hq]) + ald_q;
        e = e > 0.f ? e : 0.2f * e;
        float p = __expf(e - eself);
        s += p;
        float2 hv = *(const float2*)(hfeat + (size_t)src * 64 + 2 * lane);
        acc.x = fmaf(hv.x, p, acc.x);
        acc.y = fmaf(hv.y, p, acc.y);
    }
    float inv = __fdividef(1.f, s);
    float2 bv = *(const float2*)(bias + 2 * lane);
    float ox = fmaf(acc.x, inv, bv.x);
    float oy = fmaf(acc.y, inv, bv.y);
    ox = ox > 0.f ? ox : 0.2f * ox;
    oy = oy > 0.f ? oy : 0.2f * oy;
    *(float2*)(outf + (size_t)gw * 64 + 2 * lane) = make_float2(ox, oy);
}

// ---------------- layer-5 aggregation in x-space -----------------------------
__global__ __launch_bounds__(256) void k_agg5x(const float* __restrict__ feat, int n) {
    int gw = (blockIdx.x * blockDim.x + threadIdx.x) >> 5;
    if (gw >= n) return;
    int lane = threadIdx.x & 31;
    int h1 = lane & 7;
    int beg = g_off[gw], end = g_off[gw + 1];

    float ald_l = g_ald[gw * 8 + h1];
    float eself = g_als[gw * 8 + h1] + ald_l;
    eself = eself > 0.f ? eself : 0.2f * eself;

    float s = 1.f;
    float2 fself = *(const float2*)(feat + (size_t)gw * 64 + 2 * lane);
    float2 acc[8];
#pragma unroll
    for (int h = 0; h < 8; ++h) acc[h] = fself;

#pragma unroll 2
    for (int i = beg; i < end; ++i) {
        int src = g_csr[i];
        float e = __ldg(&g_als[src * 8 + h1]) + ald_l;
        e = e > 0.f ? e : 0.2f * e;
        float p_l = __expf(e - eself);
        s += p_l;
        float2 hv = *(const float2*)(feat + (size_t)src * 64 + 2 * lane);
#pragma unroll
        for (int h = 0; h < 8; ++h) {
            float ph = __shfl_sync(FULL, p_l, h);
            acc[h].x = fmaf(hv.x, ph, acc[h].x);
            acc[h].y = fmaf(hv.y, ph, acc[h].y);
        }
    }
    float inv_l = __fdividef(1.f, s);
    __half* out = g_aggx + (size_t)gw * 512;
#pragma unroll
    for (int h = 0; h < 8; ++h) {
        float invh = __shfl_sync(FULL, inv_l, h);
        *(__half2*)(out + h * 64 + 2 * lane) =
            __floats2half2_rn(acc[h].x * invh, acc[h].y * invh);
    }
}

// ---------------- fused layer-5 GEMM + bias + log_softmax ---------------------
__global__ __launch_bounds__(256) void k_gemm5f(const __half* __restrict__ A,
                                                const float* __restrict__ bias,
                                                float* __restrict__ outp, int n) {
    __shared__ __half As[2][128][24];
    __shared__ uint32_t Bs[2][8][40];
    int tid  = threadIdx.x;
    int lane = tid & 31, wid = tid >> 5;
    int tig = lane & 3, grp = lane >> 2;
    int row0 = blockIdx.x * 128;

    float acc[5][4] = {};

    int a_r = tid >> 1, a_part = tid & 1;

    auto stage = [&](int t, int buf) {
        int kc = t * 16;
        int gr = row0 + a_r;
        int grc = gr < n ? gr : n - 1;
        cp16(&As[buf][a_r][a_part * 8],
             A + (size_t)grc * 512 + kc + a_part * 8,
             gr < n ? 16 : 0);
        if (tid < 80) {
            int r2 = tid / 10, c4 = (tid % 10) * 4;
            cp16(&Bs[buf][r2][c4], &g_wstk[(t * 8 + r2) * 40 + c4], 16);
        }
    };

    stage(0, 0);
    cp_commit();

    for (int t = 0; t < 32; ++t) {
        if (t + 1 < 32) {
            stage(t + 1, (t + 1) & 1);
            cp_commit();
            cp_wait<1>();
        } else {
            cp_wait<0>();
        }
        __syncthreads();
        int buf = t & 1;
        const uint32_t* Au = (const uint32_t*)&As[buf][0][0];
        int r = wid * 16 + grp;
        uint32_t a0 = Au[r * 12 + tig];
        uint32_t a1 = Au[(r + 8) * 12 + tig];
        uint32_t a2 = Au[r * 12 + tig + 4];
        uint32_t a3 = Au[(r + 8) * 12 + tig + 4];
#pragma unroll
        for (int nj = 0; nj < 5; ++nj) {
            int c = nj * 8 + grp;
            uint32_t b0 = Bs[buf][tig][c];
            uint32_t b1 = Bs[buf][tig + 4][c];
            mma_f16(acc[nj], a0, a1, a2, a3, b0, b1);
        }
        __syncthreads();
    }

    int r0 = row0 + wid * 16 + grp;
#pragma unroll
    for (int half = 0; half < 2; ++half) {
        int r = r0 + half * 8;
        float val[10];
        float mx = -1e38f;
#pragma unroll
        for (int nj = 0; nj < 5; ++nj) {
            int c = nj * 8 + 2 * tig;
            float2 bv = *(const float2*)(bias + c);
            val[2 * nj]     = acc[nj][2 * half]     + bv.x;
            val[2 * nj + 1] = acc[nj][2 * half + 1] + bv.y;
            mx = fmaxf(mx, fmaxf(val[2 * nj], val[2 * nj + 1]));
        }
        mx = fmaxf(mx, __shfl_xor_sync(FULL, mx, 1));
        mx = fmaxf(mx, __shfl_xor_sync(FULL, mx, 2));
        float se = 0.f;
#pragma unroll
        for (int j = 0; j < 10; ++j) se += __expf(val[j] - mx);
        se += __shfl_xor_sync(FULL, se, 1);
        se += __shfl_xor_sync(FULL, se, 2);
        float ls = mx + logf(se);
        if (r < n) {
#pragma unroll
            for (int nj = 0; nj < 5; ++nj) {
                int c = nj * 8 + 2 * tig;
                store_pair(outp + (size_t)r * 40 + c,
                           val[2 * nj] - ls, val[2 * nj + 1] - ls);
            }
        }
    }
}

// ---------------- host ----------------
extern "C" void kernel_launch(void* const* d_in, const int* in_sizes, int n_in,
                              void* d_out, int out_size) {
    const float* x  = (const float*)d_in[0];
    const int*   ei = (const int*)d_in[1];
    const float* W[5]  = {(const float*)d_in[2],  (const float*)d_in[6],
                          (const float*)d_in[10], (const float*)d_in[14],
                          (const float*)d_in[18]};
    const float* As[5] = {(const float*)d_in[3],  (const float*)d_in[7],
                          (const float*)d_in[11], (const float*)d_in[15],
                          (const float*)d_in[19]};
    const float* Ad[5] = {(const float*)d_in[4],  (const float*)d_in[8],
                          (const float*)d_in[12], (const float*)d_in[16],
                          (const float*)d_in[20]};
    const float* Bi[5] = {(const float*)d_in[5],  (const float*)d_in[9],
                          (const float*)d_in[13], (const float*)d_in[17],
                          (const float*)d_in[21]};

    int n = in_sizes[0] / 128;
    int E = in_sizes[1] / 2;
    const int* srcp = ei;
    const int* dstp = ei + E;

    float *p_feat0, *p_feat1, *p_h;
    __half* p_aggx;
    cudaGetSymbolAddress((void**)&p_feat0, g_feat0);
    cudaGetSymbolAddress((void**)&p_feat1, g_feat1);
    cudaGetSymbolAddress((void**)&p_h,     g_hbuf);
    cudaGetSymbolAddress((void**)&p_aggx,  g_aggx);

    int nblk = (n + 1023) >> 10;
    int gemm_rows = (n + 127) / 128;
    int agg_blocks = (n + 7) / 8;

    k_zero_cnt<<<(n + 255) / 256, 256>>>(n);                                   // 0
    k_count<<<(E + 255) / 256, 256>>>(dstp, E);                                // 1
    k_scan1<<<nblk, 1024>>>(n);                                                // 2
    k_gemm<<<dim3(gemm_rows, 1), 256>>>(x, W[0], p_h, As[0], Ad[0], n, 128, 64);// 3
    k_scan2<<<1, 128>>>(nblk);                                                 // 4
    k_scan3<<<(n + 1 + 255) / 256, 256>>>(n, nblk);                            // 5
    k_fill<<<(E + 255) / 256, 256>>>(srcp, dstp, E);                           // 6

    k_agg64<<<agg_blocks, 256>>>(p_h, Bi[0], p_feat0, n);                      // 7

    const float* fin[4]  = {nullptr, p_feat0, p_feat1, p_feat0};
    float*       fout[4] = {p_feat0, p_feat1, p_feat0, p_feat1};
    for (int L = 1; L < 4; ++L) {
        k_gemm<<<dim3(gemm_rows, 1), 256>>>(fin[L], W[L], p_h,
                                            As[L], Ad[L], n, 64, 64);
        k_agg64<<<agg_blocks, 256>>>(p_h, Bi[L], fout[L], n);
    }

    // Layer 5: aggregate-then-project
    k_w5prep<<<(64 * 16 + 256 * 40 + 255) / 256, 256>>>(W[4], As[4], Ad[4]);
    k_alfeat<<<(n + 255) / 256, 256>>>(p_feat1, n);
    k_agg5x<<<agg_blocks, 256>>>(p_feat1, n);
    k_gemm5f<<<gemm_rows, 256>>>(p_aggx, Bi[4], (float*)d_out, n);
}